// round 8
// baseline (speedup 1.0000x reference)
#include <cuda_runtime.h>
#include <cuda_bf16.h>
#include <math.h>
#include <stdint.h>

#define Bn 4
#define Cn 128
#define Hn 128
#define Wn 128
#define On 128
#define Kn 9
#define KKn 1152          // Cn * Kn   (main GEMM K)
#define OKK 2304          // offset conv K: 256 ch * 9, kk = c*9+k

// scratch: sampling coordinates + modulation mask, [B][K][H][W]
__device__ float g_py[Bn * Kn * Hn * Wn];
__device__ float g_px[Bn * Kn * Hn * Wn];
__device__ float g_m [Bn * Kn * Hn * Wn];
// pre-split main weights, bf16 hi/lo, [O][KK]
__device__ __nv_bfloat16 g_whi[On * KKn];
__device__ __nv_bfloat16 g_wlo[On * KKn];
// pre-split offset-conv weights, bf16 hi/lo, [32][OKK] (rows 27-31 zero)
__device__ __nv_bfloat16 g_owhi[32 * OKK];
__device__ __nv_bfloat16 g_owlo[32 * OKK];

#define SWZ(o) ((o) ^ (((o) >> 3) & 0x70))

__device__ __forceinline__ uint32_t smem_u32(const void* p) {
    uint32_t a;
    asm("{ .reg .u64 t; cvta.to.shared.u64 t, %1; cvt.u32.u64 %0, t; }"
        : "=r"(a) : "l"(p));
    return a;
}
__device__ __forceinline__ void ldsm4(uint32_t* r, uint32_t addr) {
    asm volatile("ldmatrix.sync.aligned.m8n8.x4.shared.b16 {%0,%1,%2,%3}, [%4];"
        : "=r"(r[0]), "=r"(r[1]), "=r"(r[2]), "=r"(r[3]) : "r"(addr));
}
__device__ __forceinline__ void mma16816(float* d, const uint32_t* a,
                                         uint32_t b0, uint32_t b1) {
    asm volatile(
        "mma.sync.aligned.m16n8k16.row.col.f32.bf16.bf16.f32 "
        "{%0,%1,%2,%3}, {%4,%5,%6,%7}, {%8,%9}, {%0,%1,%2,%3};"
        : "+f"(d[0]), "+f"(d[1]), "+f"(d[2]), "+f"(d[3])
        : "r"(a[0]), "r"(a[1]), "r"(a[2]), "r"(a[3]), "r"(b0), "r"(b1));
}
__device__ __forceinline__ void cp16(uint32_t dst, const void* src) {
    asm volatile("cp.async.cg.shared.global [%0], [%1], 16;"
                 :: "r"(dst), "l"(src) : "memory");
}
#define CP_COMMIT() asm volatile("cp.async.commit_group;" ::: "memory")
#define CP_WAIT0()  asm volatile("cp.async.wait_group 0;" ::: "memory")
#define BAR_SYNC(id)   asm volatile("bar.sync %0, 512;"   :: "r"(id) : "memory")
#define BAR_ARRIVE(id) asm volatile("bar.arrive %0, 512;" :: "r"(id) : "memory")
#define MEMBAR_CTA()   asm volatile("membar.cta;" ::: "memory")

// ---------------------------------------------------------------------------
// Kernel 0a/0b: weight splits
// ---------------------------------------------------------------------------
__global__ void dcn_wsplit_kernel(const float* __restrict__ wgt) {
    int i = blockIdx.x * 256 + threadIdx.x;
    if (i < On * KKn) {
        float w = wgt[i];
        __nv_bfloat16 h = __float2bfloat16(w);
        g_whi[i] = h;
        g_wlo[i] = __float2bfloat16(w - __bfloat162float(h));
    }
}
__global__ void dcn_owsplit_kernel(const float* __restrict__ offw) {
    int i = blockIdx.x * 256 + threadIdx.x;
    if (i >= 32 * OKK) return;
    int r = i / OKK;
    float w = (r < 27) ? offw[i] : 0.f;
    __nv_bfloat16 h = __float2bfloat16(w);
    g_owhi[i] = h;
    g_owlo[i] = __float2bfloat16(w - __bfloat162float(h));
}

// ---------------------------------------------------------------------------
// Kernel 1: offset conv via HMMA, warp-specialized, 2 image rows per CTA.
// 512 threads: warps 0-7 consumers (tile 32o x 32px), warps 8-15 producers.
// B tile: 64kk x 256px (row r = yy*128 + x), hi/lo, double-buffered.
// smem: A 2x8KB @0, B 2x64KB @16384.
// ---------------------------------------------------------------------------
__global__ __launch_bounds__(512) void dcn_offset_mma(
    const float* __restrict__ inp,
    const float* __restrict__ inter,
    const float* __restrict__ offb)
{
    extern __shared__ char smem_raw[];
    char* tiles = (char*)(((uintptr_t)smem_raw + 1023) & ~(uintptr_t)1023);

    const int tid = threadIdx.x;
    const int wid = tid >> 5;
    const int lid = tid & 31;
    const int y0  = blockIdx.x * 2;
    const int b   = blockIdx.y;
    const uint32_t tbase = smem_u32(tiles);

    // ---- B gather helpers (value = direct shifted-window read) ----
    auto bload = [&](int chunk, int jg, int pxr, float* fv) {
        int yy   = pxr >> 7;
        int xloc = pxr & 127;
        #pragma unroll
        for (int j = 0; j < 8; ++j) {
            int kk = chunk * 64 + jg * 8 + j;
            int c  = kk / 9;
            int k  = kk - c * 9;
            int ky = k / 3;
            int kx = k - ky * 3;
            int yg = y0 + yy + ky - 1;
            int xg = xloc + kx - 1;
            float v = 0.f;
            if (yg >= 0 && yg < Hn && xg >= 0 && xg < Wn) {
                const float* base = (c < Cn)
                    ? inp   + ((size_t)b * Cn + c) * (Hn * Wn)
                    : inter + ((size_t)b * Cn + (c - Cn)) * (Hn * Wn);
                v = base[yg * Wn + xg];
            }
            fv[j] = v;
        }
    };
    auto bstore = [&](char* bbuf, int jg, int pxr, const float* fv) {
        uint4 vh4, vl4;
        __nv_bfloat16* vh = (__nv_bfloat16*)&vh4;
        __nv_bfloat16* vl = (__nv_bfloat16*)&vl4;
        #pragma unroll
        for (int j = 0; j < 8; ++j) {
            __nv_bfloat16 h = __float2bfloat16(fv[j]);
            vh[j] = h;
            vl[j] = __float2bfloat16(fv[j] - __bfloat162float(h));
        }
        uint32_t off = (uint32_t)(pxr * 128 + jg * 16);
        *(uint4*)(bbuf + SWZ(off))         = vh4;
        *(uint4*)(bbuf + 32768 + SWZ(off)) = vl4;
    };

    // ---- prologue: all 512 threads fill buffer 0 ----
    {
        char* A0 = tiles;
        char* B0 = tiles + 16384;
        // A: 512 uint4 (hi 256 + lo 256), 1 per thread
        {
            int i  = tid;
            if (i < 512) {
                int tt  = i >> 8;
                int rem = i & 255;
                int r   = rem >> 3;
                int j   = rem & 7;
                const char* src = (tt ? (const char*)g_owlo : (const char*)g_owhi)
                                  + r * (OKK * 2) + j * 16;
                *(uint4*)(A0 + tt * 4096 + SWZ((uint32_t)(r * 128 + j * 16)))
                    = *(const uint4*)src;
            }
        }
        // B: 16384 values / 512 thr = 4 items
        int pxr = tid & 255;
        int jb  = (tid >> 8) * 4;
        float fv[8];
        #pragma unroll
        for (int it = 0; it < 4; ++it) {
            bload(0, jb + it, pxr, fv);
            bstore(B0, jb + it, pxr, fv);
        }
    }
    __syncthreads();

    if (wid < 8) {
        // ===================== CONSUMER =====================
        const int g  = lid >> 2;
        const int t  = lid & 3;
        const int n0 = wid * 32;
        const int idx = lid >> 3, lr = lid & 7;
        const uint32_t aoff0 = (uint32_t)(((idx & 1) * 8 + lr) * 128 + (idx >> 1) * 16);
        const uint32_t aoff1 = aoff0 + 16 * 128;
        const uint32_t boff0 = (uint32_t)((n0 + (idx >> 1) * 8 + lr) * 128 + (idx & 1) * 16);
        const uint32_t boff1 = boff0 + 16 * 128;

        float acc[2][4][4];
        #pragma unroll
        for (int i = 0; i < 2; i++)
            #pragma unroll
            for (int j = 0; j < 4; j++)
                #pragma unroll
                for (int q = 0; q < 4; q++) acc[i][j][q] = 0.f;

        for (int c = 0; c < 36; ++c) {
            int s = c & 1;
            if (c) BAR_SYNC(1 + s);
            uint32_t A = tbase + (uint32_t)(s * 8192);
            uint32_t B = tbase + 16384 + (uint32_t)(s * 65536);
            uint32_t Ah = A, Al = A + 4096, Bh = B, Bl = B + 32768;
            #pragma unroll
            for (int ks = 0; ks < 4; ++ks) {
                uint32_t ah[2][4], al[2][4], bh[2][4], bl[2][4];
                uint32_t a0 = SWZ(aoff0 + ks * 32);
                uint32_t a1 = SWZ(aoff1 + ks * 32);
                uint32_t b0 = SWZ(boff0 + ks * 32);
                uint32_t b1 = SWZ(boff1 + ks * 32);
                ldsm4(ah[0], Ah + a0); ldsm4(ah[1], Ah + a1);
                ldsm4(al[0], Al + a0); ldsm4(al[1], Al + a1);
                ldsm4(bh[0], Bh + b0); ldsm4(bh[1], Bh + b1);
                ldsm4(bl[0], Bl + b0); ldsm4(bl[1], Bl + b1);
                #pragma unroll
                for (int q = 0; q < 2; ++q) {
                    #pragma unroll
                    for (int hf = 0; hf < 2; ++hf) {
                        int nt = q * 2 + hf;
                        uint32_t h0 = bh[q][2*hf], h1 = bh[q][2*hf+1];
                        uint32_t l0 = bl[q][2*hf], l1 = bl[q][2*hf+1];
                        #pragma unroll
                        for (int mt = 0; mt < 2; ++mt) {
                            mma16816(acc[mt][nt], ah[mt], h0, h1);
                            mma16816(acc[mt][nt], ah[mt], l0, l1);
                            mma16816(acc[mt][nt], al[mt], h0, h1);
                        }
                    }
                }
            }
            BAR_ARRIVE(3 + s);
        }

        // stash acc for epilogue via smem D after full-CTA sync (below)
        __syncthreads();
        float* Dsm = (float*)tiles;          // [32][260]
        #pragma unroll
        for (int mt = 0; mt < 2; ++mt) {
            int r0 = mt * 16 + g;
            int r1 = r0 + 8;
            float bo0 = (r0 < 27) ? offb[r0] : 0.f;
            float bo1 = (r1 < 27) ? offb[r1] : 0.f;
            #pragma unroll
            for (int nt = 0; nt < 4; ++nt) {
                int cx = n0 + nt * 8 + 2 * t;
                Dsm[r0 * 260 + cx]     = acc[mt][nt][0] + bo0;
                Dsm[r0 * 260 + cx + 1] = acc[mt][nt][1] + bo0;
                Dsm[r1 * 260 + cx]     = acc[mt][nt][2] + bo1;
                Dsm[r1 * 260 + cx + 1] = acc[mt][nt][3] + bo1;
            }
        }
    } else {
        // ===================== PRODUCER =====================
        const int ptid = tid - 256;
        const int pxr  = ptid;               // one px row per producer thread
        for (int cn = 1; cn < 36; ++cn) {
            int s = cn & 1;
            if (cn >= 2) BAR_SYNC(3 + s);
            char* Abuf = tiles + s * 8192;
            char* Bbuf = tiles + 16384 + (size_t)s * 65536;
            // A via cp.async: 2 x 16B per thread
            #pragma unroll
            for (int i = ptid; i < 512; i += 256) {
                int tt  = i >> 8;
                int rem = i & 255;
                int r   = rem >> 3;
                int j   = rem & 7;
                const char* src = (tt ? (const char*)g_owlo : (const char*)g_owhi)
                                  + r * (OKK * 2) + cn * 128 + j * 16;
                cp16(smem_u32(Abuf) + tt * 4096 + SWZ((uint32_t)(r * 128 + j * 16)), src);
            }
            CP_COMMIT();
            // B: 8 items of 8, 2-deep pipelined
            float fv[2][8];
            bload(cn, 0, pxr, fv[0]);
            #pragma unroll
            for (int it = 0; it < 8; ++it) {
                if (it < 7) bload(cn, it + 1, pxr, fv[(it + 1) & 1]);
                bstore(Bbuf, it, pxr, fv[it & 1]);
            }
            CP_WAIT0();
            MEMBAR_CTA();
            BAR_ARRIVE(1 + s);
        }
        __syncthreads();   // join for epilogue
    }

    __syncthreads();       // D ready
    // coordinate / mask transform for 256 px (2 rows)
    if (tid < 256) {
        float* Dsm = (float*)tiles;
        int yy = tid >> 7;
        int x  = tid & 127;
        int yq = y0 + yy;
        #pragma unroll
        for (int k = 0; k < 9; ++k) {
            float dy = Dsm[(2 * k) * 260 + tid];
            float dx = Dsm[(2 * k + 1) * 260 + tid];
            float mv = 1.f / (1.f + expf(-Dsm[(18 + k) * 260 + tid]));
            int idx2 = ((b * Kn + k) * Hn + yq) * Wn + x;
            g_py[idx2] = dy + (float)(yq - 1 + (k / 3));
            g_px[idx2] = dx + (float)(x - 1 + (k % 3));
            g_m [idx2] = mv;
        }
    }
}

// ---------------------------------------------------------------------------
// Kernel 2: main GEMM, warp-specialized. One CTA per (b,y).
// 512 threads: warps 0-7 consumers (tile 32o x 64px), warps 8-15 producers
// (bilinear gather + convert + STS, A via cp.async). Double-buffered A+B.
// smem: A 2x32KB @0, B 2x32KB @65536, tables @131072.
// ---------------------------------------------------------------------------
__global__ __launch_bounds__(512) void dcn_main_mma(
    const float* __restrict__ inp,
    const float* __restrict__ bias,
    float* __restrict__ out)
{
    extern __shared__ char smem_raw[];
    char* tiles = (char*)(((uintptr_t)smem_raw + 1023) & ~(uintptr_t)1023);
    float4*   cwgt = (float4*)(tiles + 131072);            // [9*128]
    uint32_t* cpak = (uint32_t*)(tiles + 131072 + 18432);  // [9*128]

    const int tid = threadIdx.x;
    const int wid = tid >> 5;
    const int lid = tid & 31;
    const int y   = blockIdx.x;
    const int b   = blockIdx.y;
    const uint32_t tbase = smem_u32(tiles);
    const float* binp = inp + (size_t)b * Cn * Hn * Wn;

    // ---- corner tables (all 512 threads) ----
    for (int e = tid; e < 1152; e += 512) {
        int k  = e >> 7;
        int px = e & 127;
        int gi = ((b * Kn + k) * Hn + y) * Wn + px;
        float pyv = g_py[gi];
        float pxv = g_px[gi];
        float mv  = g_m[gi];
        float y0f = floorf(pyv);
        float x0f = floorf(pxv);
        float wy = pyv - y0f;
        float wx = pxv - x0f;
        int yI = (int)y0f;
        int xI = (int)x0f;
        float vy0 = (yI >= 0  && yI <= Hn - 1) ? 1.f : 0.f;
        float vy1 = (yI >= -1 && yI <= Hn - 2) ? 1.f : 0.f;
        float vx0 = (xI >= 0  && xI <= Wn - 1) ? 1.f : 0.f;
        float vx1 = (xI >= -1 && xI <= Wn - 2) ? 1.f : 0.f;
        float w00 = (1.f - wy) * (1.f - wx) * mv * (vy0 * vx0);
        float w01 = (1.f - wy) * wx         * mv * (vy0 * vx1);
        float w10 = wy * (1.f - wx)         * mv * (vy1 * vx0);
        float w11 = wy * wx                 * mv * (vy1 * vx1);
        int y0c = min(max(yI, 0), Hn - 1);
        int y1c = min(max(yI + 1, 0), Hn - 1);
        int x0c = min(max(xI, 0), Wn - 1);
        int x1c = min(max(xI + 1, 0), Wn - 1);
        cwgt[e] = make_float4(w00, w01, w10, w11);
        cpak[e] = (uint32_t)(y0c * Wn + x0c)
                | ((uint32_t)(x1c - x0c) << 14)
                | ((uint32_t)(y1c - y0c) << 15);
    }
    __syncthreads();

    auto bload = [&](int chunk, int jg, int px0, float* cr) {
        #pragma unroll
        for (int j = 0; j < 8; ++j) {
            int kk = chunk * 64 + jg * 8 + j;
            int c9 = kk / 9;
            int k  = kk - c9 * 9;
            int e  = (k << 7) + px0;
            uint32_t p = cpak[e];
            int base = (int)(p & 0x3fff);
            int dxs  = (int)((p >> 14) & 1);
            int dyr  = ((int)((p >> 15) & 1)) << 7;
            const float* pl = binp + (c9 << 14);
            cr[4*j+0] = pl[base];
            cr[4*j+1] = pl[base + dxs];
            cr[4*j+2] = pl[base + dyr];
            cr[4*j+3] = pl[base + dyr + dxs];
        }
    };
    auto bstore = [&](char* bbuf, int chunk, int jg, int px0, const float* cr) {
        uint4 vh4, vl4;
        __nv_bfloat16* vh = (__nv_bfloat16*)&vh4;
        __nv_bfloat16* vl = (__nv_bfloat16*)&vl4;
        #pragma unroll
        for (int j = 0; j < 8; ++j) {
            int kk = chunk * 64 + jg * 8 + j;
            int c9 = kk / 9;
            int k  = kk - c9 * 9;
            int e  = (k << 7) + px0;
            float4 w = cwgt[e];
            float v = w.x * cr[4*j+0] + w.y * cr[4*j+1]
                    + w.z * cr[4*j+2] + w.w * cr[4*j+3];
            __nv_bfloat16 h = __float2bfloat16(v);
            vh[j] = h;
            vl[j] = __float2bfloat16(v - __bfloat162float(h));
        }
        uint32_t off = (uint32_t)(px0 * 128 + jg * 16);
        *(uint4*)(bbuf + SWZ(off))         = vh4;
        *(uint4*)(bbuf + 16384 + SWZ(off)) = vl4;
    };

    // ---- prologue: all 512 threads fill buffer 0 ----
    {
        char* A0 = tiles;
        char* B0 = tiles + 65536;
        #pragma unroll
        for (int i = tid; i < 2048; i += 512) {
            int tt = i >> 10;
            int r  = (i >> 3) & 127;
            int j  = i & 7;
            const char* src = (tt ? (const char*)g_wlo : (const char*)g_whi)
                              + r * 2304 + j * 16;
            *(uint4*)(A0 + tt * 16384 + SWZ((uint32_t)(r * 128 + j * 16)))
                = *(const uint4*)src;
        }
        int px0 = tid & 127;
        int jb  = (tid >> 7) * 2;
        float cr[32];
        #pragma unroll
        for (int it = 0; it < 2; ++it) {
            bload(0, jb + it, px0, cr);
            bstore(B0, 0, jb + it, px0, cr);
        }
    }
    __syncthreads();

    if (wid < 8) {
        // ===================== CONSUMER =====================
        const int g  = lid >> 2;
        const int t  = lid & 3;
        const int m0 = (wid & 3) * 32;
        const int n0 = (wid >> 2) * 64;
        const int idx = lid >> 3, lr = lid & 7;
        const uint32_t aoff0 = (uint32_t)((m0 + (idx & 1) * 8 + lr) * 128 + (idx >> 1) * 16);
        const uint32_t aoff1 = aoff0 + 16 * 128;
        uint32_t boffq[4];
        #pragma unroll
        for (int q = 0; q < 4; ++q)
            boffq[q] = (uint32_t)((n0 + q * 16 + (idx >> 1) * 8 + lr) * 128 + (idx & 1) * 16);

        float acc[2][8][4];
        #pragma unroll
        for (int i = 0; i < 2; i++)
            #pragma unroll
            for (int j = 0; j < 8; j++)
                #pragma unroll
                for (int q = 0; q < 4; q++) acc[i][j][q] = 0.f;

        for (int c = 0; c < 18; ++c) {
            int s = c & 1;
            if (c) BAR_SYNC(1 + s);
            uint32_t A = tbase + (uint32_t)(s * 32768);
            uint32_t B = tbase + 65536 + (uint32_t)(s * 32768);
            uint32_t Ah = A, Al = A + 16384, Bh = B, Bl = B + 16384;
            #pragma unroll
            for (int ks = 0; ks < 4; ++ks) {
                uint32_t ah[2][4], al[2][4];
                uint32_t a0 = SWZ(aoff0 + ks * 32);
                uint32_t a1 = SWZ(aoff1 + ks * 32);
                ldsm4(ah[0], Ah + a0); ldsm4(ah[1], Ah + a1);
                ldsm4(al[0], Al + a0); ldsm4(al[1], Al + a1);
                #pragma unroll
                for (int q = 0; q < 4; ++q) {
                    uint32_t bo = SWZ(boffq[q] + ks * 32);
                    uint32_t bh[4], bl[4];
                    ldsm4(bh, Bh + bo);
                    ldsm4(bl, Bl + bo);
                    #pragma unroll
                    for (int hf = 0; hf < 2; ++hf) {
                        int nt = q * 2 + hf;
                        uint32_t h0 = bh[2*hf], h1 = bh[2*hf+1];
                        uint32_t l0 = bl[2*hf], l1 = bl[2*hf+1];
                        #pragma unroll
                        for (int mt = 0; mt < 2; ++mt) {
                            mma16816(acc[mt][nt], ah[mt], h0, h1);
                            mma16816(acc[mt][nt], ah[mt], l0, l1);
                            mma16816(acc[mt][nt], al[mt], h0, h1);
                        }
                    }
                }
            }
            BAR_ARRIVE(3 + s);
        }

        // epilogue: add bias, store float2 pairs
        #pragma unroll
        for (int mt = 0; mt < 2; ++mt) {
            int r0 = m0 + mt * 16 + g;
            int r1 = r0 + 8;
            float bo0 = bias[r0];
            float bo1 = bias[r1];
            float* row0 = out + (((size_t)b * On + r0) * Hn + y) * Wn;
            float* row1 = out + (((size_t)b * On + r1) * Hn + y) * Wn;
            #pragma unroll
            for (int nt = 0; nt < 8; ++nt) {
                int cx = n0 + nt * 8 + 2 * t;
                float2 v0 = make_float2(acc[mt][nt][0] + bo0, acc[mt][nt][1] + bo0);
                float2 v1 = make_float2(acc[mt][nt][2] + bo1, acc[mt][nt][3] + bo1);
                *(float2*)(row0 + cx) = v0;
                *(float2*)(row1 + cx) = v1;
            }
        }
    } else {
        // ===================== PRODUCER =====================
        const int ptid = tid - 256;
        const int px0  = ptid & 127;
        const int jb   = (ptid >> 7) * 4;
        for (int cn = 1; cn < 18; ++cn) {
            int s = cn & 1;
            if (cn >= 2) BAR_SYNC(3 + s);
            char* Abuf = tiles + (size_t)s * 32768;
            char* Bbuf = tiles + 65536 + (size_t)s * 32768;
            // A via cp.async: 8 x 16B per thread
            #pragma unroll
            for (int i = ptid; i < 2048; i += 256) {
                int tt = i >> 10;
                int r  = (i >> 3) & 127;
                int j  = i & 7;
                const char* src = (tt ? (const char*)g_wlo : (const char*)g_whi)
                                  + r * 2304 + cn * 128 + j * 16;
                cp16(smem_u32(Abuf) + tt * 16384 + SWZ((uint32_t)(r * 128 + j * 16)), src);
            }
            CP_COMMIT();
            // B: 4 items, 2-deep pipelined gather
            float cr[2][32];
            bload(cn, jb, px0, cr[0]);
            #pragma unroll
            for (int it = 0; it < 4; ++it) {
                if (it < 3) bload(cn, jb + it + 1, px0, cr[(it + 1) & 1]);
                bstore(Bbuf, cn, jb + it, px0, cr[it & 1]);
            }
            CP_WAIT0();
            MEMBAR_CTA();
            BAR_ARRIVE(1 + s);
        }
    }
}

// ---------------------------------------------------------------------------
extern "C" void kernel_launch(void* const* d_in, const int* in_sizes, int n_in,
                              void* d_out, int out_size)
{
    const float* inp   = (const float*)d_in[0];
    const float* inter = (const float*)d_in[1];
    const float* offw  = (const float*)d_in[2];
    const float* offb  = (const float*)d_in[3];
    const float* wgt   = (const float*)d_in[4];
    const float* bias  = (const float*)d_in[5];
    float* out = (float*)d_out;

    dcn_wsplit_kernel<<<(On * KKn + 255) / 256, 256>>>(wgt);
    dcn_owsplit_kernel<<<(32 * OKK + 255) / 256, 256>>>(offw);

    size_t smem1 = 1024 + 16384 + 131072;   // 148,480 B
    cudaFuncSetAttribute(dcn_offset_mma,
                         cudaFuncAttributeMaxDynamicSharedMemorySize, (int)smem1);
    dcn_offset_mma<<<dim3(Hn / 2, Bn), 512, smem1>>>(inp, inter, offb);

    size_t smem2 = 1024 + 131072 + 18432 + 4608;   // 155,136 B
    cudaFuncSetAttribute(dcn_main_mma,
                         cudaFuncAttributeMaxDynamicSharedMemorySize, (int)smem2);
    dcn_main_mma<<<dim3(Hn, Bn), 512, smem2>>>(inp, bias, out);
}